// round 16
// baseline (speedup 1.0000x reference)
#include <cuda_runtime.h>
#include <stdint.h>

#define NUM_FIELDS 10
#define VOCAB      100000
#define EMBED      16            // floats per embedding row (64 bytes)
#define BATCH      16384
#define NPAIRS     45            // C(10,2)
#define BLOCK      128
#define B_PER_BLK  (BLOCK / 4)   // 32 quads per block

// triu_indices(10, k=1): pair p -> (ii[p], jj[p]) with ii < jj
__constant__ unsigned char c_ii[NPAIRS] = {
    0,0,0,0,0,0,0,0,0,
    1,1,1,1,1,1,1,1,
    2,2,2,2,2,2,2,
    3,3,3,3,3,3,
    4,4,4,4,4,
    5,5,5,5,
    6,6,6,
    7,7,
    8
};
__constant__ unsigned char c_jj[NPAIRS] = {
    1,2,3,4,5,6,7,8,9,
    2,3,4,5,6,7,8,9,
    3,4,5,6,7,8,9,
    4,5,6,7,8,9,
    5,6,7,8,9,
    6,7,8,9,
    7,8,9,
    8,9,
    9
};

// Converged kernel (thrice-reproduced: bench 34.7/34.8/35.3us) with the
// final untested policy bit flipped:
//   * gathers: __ldcg — L2-only, NO L1 allocation. Gathered lines have
//     zero L1 reuse; skipping L1 fill removes pure overhead from the
//     L1tex pipe (was 33% busy) at identical DRAM/L2 bytes.
//   * PAIR-MAJOR grid, 128-thread blocks: ~2.3 live pair slots -> best
//     measured DRAM-row/TLB locality (64/256-thread widths both worse).
//   * __stwt stores: write-through, no L2 allocate -> lowest HBM bytes.
//   * 4 lanes per (b,p): one L1tex wavefront per 64B row; stores coalesced.
// Kernel is pinned at the random-64B-gather DRAM roofline (~170MB @
// ~5.3TB/s ~= 32us); all structural levers measured neutral/worse (R3-R15).
__global__ __launch_bounds__(BLOCK)
void ffm_kernel(const int*    __restrict__ x,      // int32 (16384, 10)
                const float4* __restrict__ emb,    // (10, 1e6, 16) as float4[40M]
                float4*       __restrict__ out)    // (16384, 45, 16) as float4
{
    int q    = threadIdx.x & 3;
    int quad = threadIdx.x >> 2;                   // 0..31
    int b    = blockIdx.x * B_PER_BLK + quad;      // exact fit: 512*32 = 16384
    int p    = blockIdx.y;                         // uniform per block
    int i    = c_ii[p];
    int j    = c_jj[p];

    // broadcast within quad (these DO benefit from L1 -> default policy)
    int xi = x[b * NUM_FIELDS + i];
    int xj = x[b * NUM_FIELDS + j];
    xi = min(max(xi, 0), VOCAB - 1);
    xj = min(max(xj, 0), VOCAB - 1);

    // out[b,p] = emb[j, x[b,i]+i*V] * emb[i, x[b,j]+j*V]
    size_t rowA = (size_t)j * (NUM_FIELDS * (size_t)VOCAB) + (size_t)xi + (size_t)i * VOCAB;
    size_t rowB = (size_t)i * (NUM_FIELDS * (size_t)VOCAB) + (size_t)xj + (size_t)j * VOCAB;

    // L2-only gathers: no L1 allocation for lines that are never reused.
    float4 a = __ldcg(emb + rowA * (EMBED / 4) + q);
    float4 v = __ldcg(emb + rowB * (EMBED / 4) + q);

    float4 o;
    o.x = a.x * v.x;
    o.y = a.y * v.y;
    o.z = a.z * v.z;
    o.w = a.w * v.w;

    // Write-through, no L2 allocate: output is never read back.
    __stwt(out + ((size_t)b * NPAIRS + p) * (EMBED / 4) + q, o);
}

extern "C" void kernel_launch(void* const* d_in, const int* in_sizes, int n_in,
                              void* d_out, int out_size)
{
    const int*    x   = (const int*)d_in[0];      // indices (int32 on device)
    const float4* emb = (const float4*)d_in[1];   // float32 (10, 1e6, 16)
    float4*       out = (float4*)d_out;           // float32 (16384, 45, 16)

    dim3 grid(BATCH / B_PER_BLK, NPAIRS);         // (512, 45)
    ffm_kernel<<<grid, BLOCK>>>(x, emb, out);
}

// round 17
// speedup vs baseline: 1.0737x; 1.0737x over previous
#include <cuda_runtime.h>
#include <stdint.h>

#define NUM_FIELDS 10
#define VOCAB      100000
#define EMBED      16            // floats per embedding row (64 bytes)
#define BATCH      16384
#define NPAIRS     45            // C(10,2)
#define BLOCK      128
#define B_PER_BLK  (BLOCK / 4)   // 32 quads per block

// triu_indices(10, k=1): pair p -> (ii[p], jj[p]) with ii < jj
__constant__ unsigned char c_ii[NPAIRS] = {
    0,0,0,0,0,0,0,0,0,
    1,1,1,1,1,1,1,1,
    2,2,2,2,2,2,2,
    3,3,3,3,3,3,
    4,4,4,4,4,
    5,5,5,5,
    6,6,6,
    7,7,
    8
};
__constant__ unsigned char c_jj[NPAIRS] = {
    1,2,3,4,5,6,7,8,9,
    2,3,4,5,6,7,8,9,
    3,4,5,6,7,8,9,
    4,5,6,7,8,9,
    5,6,7,8,9,
    6,7,8,9,
    7,8,9,
    8,9,
    9
};

// FINAL converged kernel — winner on every measured axis (R3-R16 matrix):
//   * PAIR-MAJOR grid, 128-thread blocks: resident CTAs span ~2.3 pair
//     slots (~30MB live gather footprint) -> best DRAM-row/TLB locality.
//     (b-major +6us; 64-thread +0.6us; 256-thread +1.3us)
//   * __ldcs gathers: evict-first but L1-ALLOCATING — the quad-per-row
//     mapping gets real L1 hits from neighboring rows sharing 128B lines
//     within the tight pair window. (__ldg +2us; __ldcg L1-bypass +3us)
//   * __stwt stores: write-through, no L2 allocate -> lowest HBM bytes
//     (~170MB vs ~182MB allocating). Output is never read back.
//   * 4 lanes per (b,p): lane q loads float4 q of both rows -> one L1tex
//     wavefront per 64B row; output stores fully coalesced.
// Pinned at the random-64B-gather DRAM roofline: 170MB @ ~5.3TB/s ≈ 32us
// kernel time; DRAM ~66% is the sole binding resource (issue 16%, fma 6%).
// Reproduced three times: bench 34.7/34.8/35.3us, ncu 31.9/32.6/33.1us.
__global__ __launch_bounds__(BLOCK)
void ffm_kernel(const int*    __restrict__ x,      // int32 (16384, 10)
                const float4* __restrict__ emb,    // (10, 1e6, 16) as float4[40M]
                float4*       __restrict__ out)    // (16384, 45, 16) as float4
{
    int q    = threadIdx.x & 3;
    int quad = threadIdx.x >> 2;                   // 0..31
    int b    = blockIdx.x * B_PER_BLK + quad;      // exact fit: 512*32 = 16384
    int p    = blockIdx.y;                         // uniform per block
    int i    = c_ii[p];
    int j    = c_jj[p];

    // broadcast within quad
    int xi = x[b * NUM_FIELDS + i];
    int xj = x[b * NUM_FIELDS + j];
    xi = min(max(xi, 0), VOCAB - 1);
    xj = min(max(xj, 0), VOCAB - 1);

    // out[b,p] = emb[j, x[b,i]+i*V] * emb[i, x[b,j]+j*V]
    size_t rowA = (size_t)j * (NUM_FIELDS * (size_t)VOCAB) + (size_t)xi + (size_t)i * VOCAB;
    size_t rowB = (size_t)i * (NUM_FIELDS * (size_t)VOCAB) + (size_t)xj + (size_t)j * VOCAB;

    // Evict-first streaming loads (L1-allocating).
    float4 a = __ldcs(emb + rowA * (EMBED / 4) + q);
    float4 v = __ldcs(emb + rowB * (EMBED / 4) + q);

    float4 o;
    o.x = a.x * v.x;
    o.y = a.y * v.y;
    o.z = a.z * v.z;
    o.w = a.w * v.w;

    // Write-through, no L2 allocate: output is never read back.
    __stwt(out + ((size_t)b * NPAIRS + p) * (EMBED / 4) + q, o);
}

extern "C" void kernel_launch(void* const* d_in, const int* in_sizes, int n_in,
                              void* d_out, int out_size)
{
    const int*    x   = (const int*)d_in[0];      // indices (int32 on device)
    const float4* emb = (const float4*)d_in[1];   // float32 (10, 1e6, 16)
    float4*       out = (float4*)d_out;           // float32 (16384, 45, 16)

    dim3 grid(BATCH / B_PER_BLK, NPAIRS);         // (512, 45)
    ffm_kernel<<<grid, BLOCK>>>(x, emb, out);
}